// round 2
// baseline (speedup 1.0000x reference)
#include <cuda_runtime.h>
#include <math.h>

#define M_TOK   4096     // B*L
#define D_MODEL 256
#define HDIM    512      // H*DH
#define L_SEQ   512
#define NHEAD   8
#define DHEAD   64
#define DEPTH_N 16
#define INNER_N 1024

// ---------------- scratch (device globals; no allocation allowed) -------------
__device__ float g_x   [M_TOK * D_MODEL];
__device__ float g_h   [M_TOK * D_MODEL];
__device__ float g_q   [M_TOK * HDIM];
__device__ float g_k   [M_TOK * HDIM];
__device__ float g_v   [M_TOK * HDIM];
__device__ float g_attn[M_TOK * HDIM];
__device__ float g_u   [M_TOK * 2 * INNER_N];
__device__ float g_ua  [M_TOK * INNER_N];

// ---------------- LayerNorm helper (blockDim.x == 256 == D_MODEL) ------------
__device__ __forceinline__ void ln_write(float v, const float* __restrict__ g,
                                         const float* __restrict__ b,
                                         float* __restrict__ y, int row) {
    int d = threadIdx.x;
    float s = v, s2 = v * v;
    #pragma unroll
    for (int o = 16; o > 0; o >>= 1) {
        s  += __shfl_down_sync(0xffffffffu, s,  o);
        s2 += __shfl_down_sync(0xffffffffu, s2, o);
    }
    __shared__ float ws[8], ws2[8];
    __shared__ float mean_s, inv_s;
    int w = threadIdx.x >> 5, lane = threadIdx.x & 31;
    if (lane == 0) { ws[w] = s; ws2[w] = s2; }
    __syncthreads();
    if (threadIdx.x == 0) {
        float t = 0.f, t2 = 0.f;
        #pragma unroll
        for (int i = 0; i < 8; i++) { t += ws[i]; t2 += ws2[i]; }
        float mu  = t  * (1.f / 256.f);
        float var = t2 * (1.f / 256.f) - mu * mu;
        mean_s = mu;
        inv_s  = rsqrtf(var + 1e-5f);
    }
    __syncthreads();
    y[(size_t)row * D_MODEL + d] = (v - mean_s) * inv_s * g[d] + b[d];
}

__global__ void embed_ln_kernel(const int* __restrict__ seq,
                                const float* __restrict__ emb,
                                const float* __restrict__ g,
                                const float* __restrict__ b,
                                float* __restrict__ y) {
    int row = blockIdx.x;
    float v = emb[(size_t)seq[row] * D_MODEL + threadIdx.x];
    ln_write(v, g, b, y, row);
}

__global__ void ln_kernel(const float* __restrict__ x,
                          const float* __restrict__ g,
                          const float* __restrict__ b,
                          float* __restrict__ y) {
    int row = blockIdx.x;
    float v = x[(size_t)row * D_MODEL + threadIdx.x];
    ln_write(v, g, b, y, row);
}

// ---------------- tiled fp32 GEMM: C[M,N] = A[M,K] @ W[K,N] (+bias)(+res) ----
// 64x64 tile, BK=16, 256 threads, 4x4 register blocking. Requires M%64==0,
// N%64==0, K%16==0 (true for all uses here).
__global__ void gemm_kernel(const float* __restrict__ A,
                            const float* __restrict__ W,
                            const float* __restrict__ bias,
                            const float* __restrict__ res,
                            float* __restrict__ C, int N, int K) {
    __shared__ float As[16][68];
    __shared__ float Ws[16][68];
    const int tid = threadIdx.x;
    const int tx = tid & 15, ty = tid >> 4;
    const int bm = blockIdx.y << 6, bn = blockIdx.x << 6;
    const int ar = tid >> 2, aq = tid & 3;
    const int wr = tid >> 4, wc = tid & 15;

    float acc[4][4] = {};
    for (int k0 = 0; k0 < K; k0 += 16) {
        float4 av = *(const float4*)(A + (size_t)(bm + ar) * K + k0 + aq * 4);
        float4 wv = *(const float4*)(W + (size_t)(k0 + wr) * N + bn + wc * 4);
        As[aq * 4 + 0][ar] = av.x;
        As[aq * 4 + 1][ar] = av.y;
        As[aq * 4 + 2][ar] = av.z;
        As[aq * 4 + 3][ar] = av.w;
        *(float4*)&Ws[wr][wc * 4] = wv;
        __syncthreads();
        #pragma unroll
        for (int kk = 0; kk < 16; kk++) {
            float a0 = As[kk][ty * 4 + 0];
            float a1 = As[kk][ty * 4 + 1];
            float a2 = As[kk][ty * 4 + 2];
            float a3 = As[kk][ty * 4 + 3];
            float b0 = Ws[kk][tx * 4 + 0];
            float b1 = Ws[kk][tx * 4 + 1];
            float b2 = Ws[kk][tx * 4 + 2];
            float b3 = Ws[kk][tx * 4 + 3];
            acc[0][0] += a0 * b0; acc[0][1] += a0 * b1; acc[0][2] += a0 * b2; acc[0][3] += a0 * b3;
            acc[1][0] += a1 * b0; acc[1][1] += a1 * b1; acc[1][2] += a1 * b2; acc[1][3] += a1 * b3;
            acc[2][0] += a2 * b0; acc[2][1] += a2 * b1; acc[2][2] += a2 * b2; acc[2][3] += a2 * b3;
            acc[3][0] += a3 * b0; acc[3][1] += a3 * b1; acc[3][2] += a3 * b2; acc[3][3] += a3 * b3;
        }
        __syncthreads();
    }
    #pragma unroll
    for (int r = 0; r < 4; r++) {
        int m = bm + ty * 4 + r;
        #pragma unroll
        for (int c = 0; c < 4; c++) {
            int n = bn + tx * 4 + c;
            float v = acc[r][c];
            if (bias) v += bias[n];
            if (res)  v += res[(size_t)m * N + n];
            C[(size_t)m * N + n] = v;
        }
    }
}

// ---------------- attention: per-(b,h) 64-query tile, full-row softmax -------
#define SP 514   // score row stride (bank-conflict mitigation)

__global__ void attn_kernel(const float* __restrict__ q,
                            const float* __restrict__ k,
                            const float* __restrict__ v,
                            const int* __restrict__ mask,   // int32 bool
                            float* __restrict__ o) {
    extern __shared__ float sm[];
    float* Qs = sm;                   // [64 d][68]  (transposed: [d][i])
    float* Ks = sm + 64 * 68;         // [64 d][68]  ([d][j])
    float* Vs = sm + 2 * 64 * 68;     // [64 j][68]  ([j][d])
    float* S  = sm + 3 * 64 * 68;     // [64 i][SP]
    float* red    = S + 64 * SP;      // [256]
    float* rowsum = red + 256;        // [64]
    float* rowmax = rowsum + 64;      // [64]

    const int tid = threadIdx.x;
    const int tx = tid & 15, ty = tid >> 4;
    const int qt = blockIdx.x;            // query tile 0..7
    const int b  = blockIdx.y >> 3;
    const int h  = blockIdx.y & 7;
    const float slope = exp2f(-(float)(h + 1));   // H=8 -> 2^-(h+1)
    const float scale = 0.125f;                   // DH^-0.5

    // load Q tile (transposed into [d][i])
    {
        int i = tid >> 2, quarter = tid & 3;
        const float* qp = q + (size_t)(b * L_SEQ + qt * 64 + i) * HDIM + h * DHEAD + quarter * 16;
        #pragma unroll
        for (int c2 = 0; c2 < 4; c2++) {
            float4 vv = *(const float4*)(qp + c2 * 4);
            int d = quarter * 16 + c2 * 4;
            Qs[(d + 0) * 68 + i] = vv.x;
            Qs[(d + 1) * 68 + i] = vv.y;
            Qs[(d + 2) * 68 + i] = vv.z;
            Qs[(d + 3) * 68 + i] = vv.w;
        }
    }

    // pass 1: S = Q K^T * scale + alibi, masked
    for (int kt = 0; kt < 8; kt++) {
        __syncthreads();
        {
            int j = tid >> 2, quarter = tid & 3;
            const float* kp = k + (size_t)(b * L_SEQ + kt * 64 + j) * HDIM + h * DHEAD + quarter * 16;
            #pragma unroll
            for (int c2 = 0; c2 < 4; c2++) {
                float4 vv = *(const float4*)(kp + c2 * 4);
                int d = quarter * 16 + c2 * 4;
                Ks[(d + 0) * 68 + j] = vv.x;
                Ks[(d + 1) * 68 + j] = vv.y;
                Ks[(d + 2) * 68 + j] = vv.z;
                Ks[(d + 3) * 68 + j] = vv.w;
            }
        }
        __syncthreads();
        float acc[4][4] = {};
        #pragma unroll
        for (int dd = 0; dd < 64; dd++) {
            float a0 = Qs[dd * 68 + ty * 4 + 0];
            float a1 = Qs[dd * 68 + ty * 4 + 1];
            float a2 = Qs[dd * 68 + ty * 4 + 2];
            float a3 = Qs[dd * 68 + ty * 4 + 3];
            float b0 = Ks[dd * 68 + tx * 4 + 0];
            float b1 = Ks[dd * 68 + tx * 4 + 1];
            float b2 = Ks[dd * 68 + tx * 4 + 2];
            float b3 = Ks[dd * 68 + tx * 4 + 3];
            acc[0][0] += a0 * b0; acc[0][1] += a0 * b1; acc[0][2] += a0 * b2; acc[0][3] += a0 * b3;
            acc[1][0] += a1 * b0; acc[1][1] += a1 * b1; acc[1][2] += a1 * b2; acc[1][3] += a1 * b3;
            acc[2][0] += a2 * b0; acc[2][1] += a2 * b1; acc[2][2] += a2 * b2; acc[2][3] += a2 * b3;
            acc[3][0] += a3 * b0; acc[3][1] += a3 * b1; acc[3][2] += a3 * b2; acc[3][3] += a3 * b3;
        }
        #pragma unroll
        for (int r = 0; r < 4; r++) {
            int i = ty * 4 + r;
            int ig = qt * 64 + i;
            #pragma unroll
            for (int c = 0; c < 4; c++) {
                int jg = kt * 64 + tx * 4 + c;
                float s;
                if (mask[b * L_SEQ + jg] != 0)
                    s = acc[r][c] * scale - slope * fabsf((float)(ig - jg));
                else
                    s = -1e9f;
                S[i * SP + jg] = s;
            }
        }
    }
    __syncthreads();

    // pass 2: softmax (keep exp in S, divide output by rowsum later)
    {
        int r = tid >> 2, p = tid & 3;
        float mx = -3e38f;
        for (int j = p * 128; j < p * 128 + 128; j++) mx = fmaxf(mx, S[r * SP + j]);
        red[r * 4 + p] = mx;
        __syncthreads();
        if (p == 0)
            rowmax[r] = fmaxf(fmaxf(red[r * 4], red[r * 4 + 1]),
                              fmaxf(red[r * 4 + 2], red[r * 4 + 3]));
        __syncthreads();
        float rm = rowmax[r];
        float sum = 0.f;
        for (int j = p * 128; j < p * 128 + 128; j++) {
            float e = __expf(S[r * SP + j] - rm);
            S[r * SP + j] = e;
            sum += e;
        }
        __syncthreads();           // all rowmax reads done before red reuse
        red[r * 4 + p] = sum;
        __syncthreads();
        if (p == 0)
            rowsum[r] = red[r * 4] + red[r * 4 + 1] + red[r * 4 + 2] + red[r * 4 + 3];
    }

    // pass 3: O = A @ V
    float oacc[4][4] = {};
    for (int vt = 0; vt < 8; vt++) {
        __syncthreads();
        {
            int j = tid >> 2, quarter = tid & 3;
            const float* vp = v + (size_t)(b * L_SEQ + vt * 64 + j) * HDIM + h * DHEAD + quarter * 16;
            #pragma unroll
            for (int c2 = 0; c2 < 4; c2++) {
                float4 vv = *(const float4*)(vp + c2 * 4);
                *(float4*)&Vs[j * 68 + quarter * 16 + c2 * 4] = vv;
            }
        }
        __syncthreads();
        #pragma unroll
        for (int jj = 0; jj < 64; jj++) {
            float a0 = S[(ty * 4 + 0) * SP + vt * 64 + jj];
            float a1 = S[(ty * 4 + 1) * SP + vt * 64 + jj];
            float a2 = S[(ty * 4 + 2) * SP + vt * 64 + jj];
            float a3 = S[(ty * 4 + 3) * SP + vt * 64 + jj];
            float b0 = Vs[jj * 68 + tx * 4 + 0];
            float b1 = Vs[jj * 68 + tx * 4 + 1];
            float b2 = Vs[jj * 68 + tx * 4 + 2];
            float b3 = Vs[jj * 68 + tx * 4 + 3];
            oacc[0][0] += a0 * b0; oacc[0][1] += a0 * b1; oacc[0][2] += a0 * b2; oacc[0][3] += a0 * b3;
            oacc[1][0] += a1 * b0; oacc[1][1] += a1 * b1; oacc[1][2] += a1 * b2; oacc[1][3] += a1 * b3;
            oacc[2][0] += a2 * b0; oacc[2][1] += a2 * b1; oacc[2][2] += a2 * b2; oacc[2][3] += a2 * b3;
            oacc[3][0] += a3 * b0; oacc[3][1] += a3 * b1; oacc[3][2] += a3 * b2; oacc[3][3] += a3 * b3;
        }
    }
    #pragma unroll
    for (int r = 0; r < 4; r++) {
        int i = ty * 4 + r;
        float inv = 1.f / rowsum[i];
        size_t tok = (size_t)(b * L_SEQ + qt * 64 + i);
        #pragma unroll
        for (int c = 0; c < 4; c++)
            o[tok * HDIM + h * DHEAD + tx * 4 + c] = oacc[r][c] * inv;
    }
}

// ---------------- GEGLU: ua = val * gelu(gate), exact gelu -------------------
__global__ void glu_kernel(const float* __restrict__ u, float* __restrict__ ua) {
    int idx = blockIdx.x * blockDim.x + threadIdx.x;   // 4096*1024 total
    int m = idx >> 10, i = idx & 1023;
    float val  = u[(size_t)m * 2048 + i];
    float gate = u[(size_t)m * 2048 + 1024 + i];
    ua[idx] = val * gate * normcdff(gate);
}

// ---------------- final projection to 2 logits -------------------------------
__global__ void out_kernel(const float* __restrict__ hh,
                           const float* __restrict__ Wout,
                           const float* __restrict__ bout,
                           float* __restrict__ out) {
    int row = blockIdx.x;
    int d = threadIdx.x;
    float v = hh[(size_t)row * D_MODEL + d];
    float s0 = v * Wout[d * 2 + 0];
    float s1 = v * Wout[d * 2 + 1];
    #pragma unroll
    for (int o2 = 16; o2 > 0; o2 >>= 1) {
        s0 += __shfl_down_sync(0xffffffffu, s0, o2);
        s1 += __shfl_down_sync(0xffffffffu, s1, o2);
    }
    __shared__ float w0[8], w1[8];
    int w = threadIdx.x >> 5, lane = threadIdx.x & 31;
    if (lane == 0) { w0[w] = s0; w1[w] = s1; }
    __syncthreads();
    if (threadIdx.x == 0) {
        float t0 = 0.f, t1 = 0.f;
        #pragma unroll
        for (int i = 0; i < 8; i++) { t0 += w0[i]; t1 += w1[i]; }
        out[row * 2 + 0] = t0 + bout[0];
        out[row * 2 + 1] = t1 + bout[1];
    }
}

// ---------------- host orchestration -----------------------------------------
extern "C" void kernel_launch(void* const* d_in, const int* in_sizes, int n_in,
                              void* d_out, int out_size) {
    (void)in_sizes; (void)n_in; (void)out_size;
    const int*   seq  = (const int*)d_in[0];
    const int*   mask = (const int*)d_in[1];
    const float* emb  = (const float*)d_in[2];
    const float* png  = (const float*)d_in[3];
    const float* pnb  = (const float*)d_in[4];
    const float* ln1g = (const float*)d_in[5];
    const float* ln1b = (const float*)d_in[6];
    const float* Wq   = (const float*)d_in[7];
    const float* Wk   = (const float*)d_in[8];
    const float* Wv   = (const float*)d_in[9];
    const float* Wo   = (const float*)d_in[10];
    const float* ln2g = (const float*)d_in[11];
    const float* ln2b = (const float*)d_in[12];
    const float* W1   = (const float*)d_in[13];
    const float* b1   = (const float*)d_in[14];
    const float* W2   = (const float*)d_in[15];
    const float* b2   = (const float*)d_in[16];
    const float* fng  = (const float*)d_in[17];
    const float* fnb  = (const float*)d_in[18];
    const float* Wout = (const float*)d_in[19];
    const float* bout = (const float*)d_in[20];

    float *x, *h, *qb, *kb, *vb, *ab, *ub, *uab;
    cudaGetSymbolAddress((void**)&x,   g_x);
    cudaGetSymbolAddress((void**)&h,   g_h);
    cudaGetSymbolAddress((void**)&qb,  g_q);
    cudaGetSymbolAddress((void**)&kb,  g_k);
    cudaGetSymbolAddress((void**)&vb,  g_v);
    cudaGetSymbolAddress((void**)&ab,  g_attn);
    cudaGetSymbolAddress((void**)&ub,  g_u);
    cudaGetSymbolAddress((void**)&uab, g_ua);

    const int attn_smem = (3 * 64 * 68 + 64 * SP + 256 + 64 + 64) * (int)sizeof(float);
    cudaFuncSetAttribute(attn_kernel, cudaFuncAttributeMaxDynamicSharedMemorySize, attn_smem);

    embed_ln_kernel<<<M_TOK, 256>>>(seq, emb, png, pnb, x);

    for (int l = 0; l < DEPTH_N; l++) {
        const float* wq  = Wq  + (size_t)l * D_MODEL * HDIM;
        const float* wk  = Wk  + (size_t)l * D_MODEL * HDIM;
        const float* wv  = Wv  + (size_t)l * D_MODEL * HDIM;
        const float* wo  = Wo  + (size_t)l * HDIM * D_MODEL;
        const float* w1  = W1  + (size_t)l * D_MODEL * 2 * INNER_N;
        const float* bb1 = b1  + (size_t)l * 2 * INNER_N;
        const float* w2  = W2  + (size_t)l * INNER_N * D_MODEL;
        const float* bb2 = b2  + (size_t)l * D_MODEL;

        ln_kernel<<<M_TOK, 256>>>(x, ln1g + l * D_MODEL, ln1b + l * D_MODEL, h);

        gemm_kernel<<<dim3(HDIM / 64, M_TOK / 64), 256>>>(h, wq, nullptr, nullptr, qb, HDIM, D_MODEL);
        gemm_kernel<<<dim3(HDIM / 64, M_TOK / 64), 256>>>(h, wk, nullptr, nullptr, kb, HDIM, D_MODEL);
        gemm_kernel<<<dim3(HDIM / 64, M_TOK / 64), 256>>>(h, wv, nullptr, nullptr, vb, HDIM, D_MODEL);

        attn_kernel<<<dim3(L_SEQ / 64, 8 * NHEAD), 256, attn_smem>>>(qb, kb, vb, mask, ab);

        // x = x + attn @ Wo
        gemm_kernel<<<dim3(D_MODEL / 64, M_TOK / 64), 256>>>(ab, wo, nullptr, x, x, D_MODEL, HDIM);

        ln_kernel<<<M_TOK, 256>>>(x, ln2g + l * D_MODEL, ln2b + l * D_MODEL, h);

        // u = h @ W1 + b1
        gemm_kernel<<<dim3(2 * INNER_N / 64, M_TOK / 64), 256>>>(h, w1, bb1, nullptr, ub, 2 * INNER_N, D_MODEL);

        glu_kernel<<<(M_TOK * INNER_N) / 256, 256>>>(ub, uab);

        // x = x + ua @ W2 + b2
        gemm_kernel<<<dim3(D_MODEL / 64, M_TOK / 64), 256>>>(uab, w2, bb2, x, x, D_MODEL, INNER_N);
    }

    ln_kernel<<<M_TOK, 256>>>(x, fng, fnb, h);
    out_kernel<<<M_TOK, 256>>>(h, Wout, bout, (float*)d_out);
}

// round 3
// speedup vs baseline: 1.2535x; 1.2535x over previous
#include <cuda_runtime.h>
#include <math.h>
#include <mma.h>

using namespace nvcuda;

#define M_TOK   4096     // B*L
#define D_MODEL 256
#define HDIM    512      // H*DH
#define L_SEQ   512
#define NHEAD   8
#define DHEAD   64
#define DEPTH_N 16
#define INNER_N 1024

// ---------------- scratch (device globals; no allocation allowed) -------------
__device__ float g_x   [M_TOK * D_MODEL];
__device__ float g_h   [M_TOK * D_MODEL];
__device__ float g_t   [M_TOK * D_MODEL];
__device__ float g_q   [M_TOK * HDIM];
__device__ float g_k   [M_TOK * HDIM];
__device__ float g_v   [M_TOK * HDIM];
__device__ float g_attn[M_TOK * HDIM];
__device__ float g_u   [M_TOK * 2 * INNER_N];
__device__ float g_ua  [M_TOK * INNER_N];

// ---------------- LayerNorm helper (blockDim.x == 256 == D_MODEL) ------------
__device__ __forceinline__ void ln_write(float v, const float* __restrict__ g,
                                         const float* __restrict__ b,
                                         float* __restrict__ y, int row) {
    int d = threadIdx.x;
    float s = v, s2 = v * v;
    #pragma unroll
    for (int o = 16; o > 0; o >>= 1) {
        s  += __shfl_down_sync(0xffffffffu, s,  o);
        s2 += __shfl_down_sync(0xffffffffu, s2, o);
    }
    __shared__ float ws[8], ws2[8];
    __shared__ float mean_s, inv_s;
    int w = threadIdx.x >> 5, lane = threadIdx.x & 31;
    if (lane == 0) { ws[w] = s; ws2[w] = s2; }
    __syncthreads();
    if (threadIdx.x == 0) {
        float t = 0.f, t2 = 0.f;
        #pragma unroll
        for (int i = 0; i < 8; i++) { t += ws[i]; t2 += ws2[i]; }
        float mu  = t  * (1.f / 256.f);
        float var = t2 * (1.f / 256.f) - mu * mu;
        mean_s = mu;
        inv_s  = rsqrtf(var + 1e-5f);
    }
    __syncthreads();
    y[(size_t)row * D_MODEL + d] = (v - mean_s) * inv_s * g[d] + b[d];
}

__global__ void embed_ln_kernel(const int* __restrict__ seq,
                                const float* __restrict__ emb,
                                const float* __restrict__ g,
                                const float* __restrict__ b,
                                float* __restrict__ y) {
    int row = blockIdx.x;
    float v = emb[(size_t)seq[row] * D_MODEL + threadIdx.x];
    ln_write(v, g, b, y, row);
}

__global__ void ln_kernel(const float* __restrict__ x,
                          const float* __restrict__ g,
                          const float* __restrict__ b,
                          float* __restrict__ y) {
    int row = blockIdx.x;
    float v = x[(size_t)row * D_MODEL + threadIdx.x];
    ln_write(v, g, b, y, row);
}

// x[row] += t[row] (+bias); then y[row] = LN(x[row])
__global__ void add_ln_kernel(float* __restrict__ x,
                              const float* __restrict__ t,
                              const float* __restrict__ bias,
                              const float* __restrict__ g,
                              const float* __restrict__ b,
                              float* __restrict__ y) {
    int row = blockIdx.x;
    int d = threadIdx.x;
    size_t idx = (size_t)row * D_MODEL + d;
    float v = x[idx] + t[idx];
    if (bias) v += bias[d];
    x[idx] = v;
    ln_write(v, g, b, y, row);
}

// ---------------- tf32 WMMA GEMM: C[M,N] = A[M,K] @ W[K,N] (raw product) -----
// Block tile 128x64, 256 threads = 8 warps (4 m x 2 n), warp tile 32x32.
// M=4096 fixed; K multiple of 32; N multiple of 64.
__global__ void gemm_tf32(const float* __restrict__ A,
                          const float* __restrict__ W,
                          float* __restrict__ C, int N, int K) {
    __shared__ float As[128][40];
    __shared__ float Bs[32][68];
    const int tid = threadIdx.x;
    const int warp = tid >> 5;
    const int wm = warp & 3, wn = warp >> 2;
    const int bm = blockIdx.y << 7, bn = blockIdx.x << 6;

    wmma::fragment<wmma::accumulator, 16, 16, 8, float> acc[2][2];
    #pragma unroll
    for (int i = 0; i < 2; i++)
        #pragma unroll
        for (int j = 0; j < 2; j++)
            wmma::fill_fragment(acc[i][j], 0.0f);

    const int ar = tid >> 3, ac = (tid & 7) * 4;
    const int br = tid >> 4, bc = (tid & 15) * 4;

    for (int k0 = 0; k0 < K; k0 += 32) {
        #pragma unroll
        for (int i = 0; i < 4; i++) {
            float4 v = *(const float4*)(A + (size_t)(bm + ar + i * 32) * K + k0 + ac);
            *(float4*)&As[ar + i * 32][ac] = v;
        }
        #pragma unroll
        for (int i = 0; i < 2; i++) {
            float4 v = *(const float4*)(W + (size_t)(k0 + br + i * 16) * N + bn + bc);
            *(float4*)&Bs[br + i * 16][bc] = v;
        }
        __syncthreads();
        #pragma unroll
        for (int kk = 0; kk < 4; kk++) {
            wmma::fragment<wmma::matrix_a, 16, 16, 8, wmma::precision::tf32, wmma::row_major> af[2];
            wmma::fragment<wmma::matrix_b, 16, 16, 8, wmma::precision::tf32, wmma::row_major> bf[2];
            #pragma unroll
            for (int i = 0; i < 2; i++) {
                wmma::load_matrix_sync(af[i], &As[wm * 32 + i * 16][kk * 8], 40);
                #pragma unroll
                for (int e = 0; e < af[i].num_elements; e++)
                    af[i].x[e] = wmma::__float_to_tf32(af[i].x[e]);
            }
            #pragma unroll
            for (int j = 0; j < 2; j++) {
                wmma::load_matrix_sync(bf[j], &Bs[kk * 8][wn * 32 + j * 16], 68);
                #pragma unroll
                for (int e = 0; e < bf[j].num_elements; e++)
                    bf[j].x[e] = wmma::__float_to_tf32(bf[j].x[e]);
            }
            #pragma unroll
            for (int i = 0; i < 2; i++)
                #pragma unroll
                for (int j = 0; j < 2; j++)
                    wmma::mma_sync(acc[i][j], af[i], bf[j], acc[i][j]);
        }
        __syncthreads();
    }
    #pragma unroll
    for (int i = 0; i < 2; i++)
        #pragma unroll
        for (int j = 0; j < 2; j++)
            wmma::store_matrix_sync(C + (size_t)(bm + wm * 32 + i * 16) * N + bn + wn * 32 + j * 16,
                                    acc[i][j], N, wmma::mem_row_major);
}

// ---------------- attention: WMMA QK^T + softmax + WMMA PV -------------------
#define SP 516   // score row stride (multiple of 4 for wmma; 4-bank skew)

__global__ void attn_kernel(const float* __restrict__ q,
                            const float* __restrict__ k,
                            const float* __restrict__ v,
                            const int* __restrict__ mask,
                            float* __restrict__ o) {
    extern __shared__ float sm[];
    float* Qs = sm;                     // [64][72]
    float* Ks = sm + 64 * 72;           // [64][72] (reused for V)
    float* S  = sm + 2 * 64 * 72;       // [64][SP]
    float* red    = S + 64 * SP;        // [256]
    float* rowsum = red + 256;          // [64]
    float* rowmax = rowsum + 64;        // [64]

    const int tid = threadIdx.x;
    const int warp = tid >> 5;
    const int wm = warp & 3;            // row tile: rows wm*16..+16
    const int wn = warp >> 2;           // col strip: 32 wide
    const int qt = blockIdx.x;
    const int b  = blockIdx.y >> 3;
    const int h  = blockIdx.y & 7;
    const float slope = exp2f(-(float)(h + 1));
    const float scale = 0.125f;

    // load Q tile [64 rows][64 dims], row-major, ld 72
    {
        int r = tid >> 2, c = (tid & 3) * 4;
        const float* qp = q + (size_t)(b * L_SEQ + qt * 64 + r) * HDIM + h * DHEAD;
        #pragma unroll
        for (int p = 0; p < 4; p++)
            *(float4*)&Qs[r * 72 + c + p * 16] = *(const float4*)(qp + c + p * 16);
    }

    // pass 1: raw scores S = Q K^T via wmma
    for (int kt = 0; kt < 8; kt++) {
        __syncthreads();
        {
            int r = tid >> 2, c = (tid & 3) * 4;
            const float* kp = k + (size_t)(b * L_SEQ + kt * 64 + r) * HDIM + h * DHEAD;
            #pragma unroll
            for (int p = 0; p < 4; p++)
                *(float4*)&Ks[r * 72 + c + p * 16] = *(const float4*)(kp + c + p * 16);
        }
        __syncthreads();
        wmma::fragment<wmma::accumulator, 16, 16, 8, float> sacc[2];
        wmma::fill_fragment(sacc[0], 0.0f);
        wmma::fill_fragment(sacc[1], 0.0f);
        #pragma unroll
        for (int kk = 0; kk < 8; kk++) {
            wmma::fragment<wmma::matrix_a, 16, 16, 8, wmma::precision::tf32, wmma::row_major> af;
            wmma::load_matrix_sync(af, &Qs[(wm * 16) * 72 + kk * 8], 72);
            #pragma unroll
            for (int e = 0; e < af.num_elements; e++)
                af.x[e] = wmma::__float_to_tf32(af.x[e]);
            #pragma unroll
            for (int j = 0; j < 2; j++) {
                // B[k=d][n=j] = K[j][d]: col-major over Ks
                wmma::fragment<wmma::matrix_b, 16, 16, 8, wmma::precision::tf32, wmma::col_major> bf;
                wmma::load_matrix_sync(bf, &Ks[(wn * 32 + j * 16) * 72 + kk * 8], 72);
                #pragma unroll
                for (int e = 0; e < bf.num_elements; e++)
                    bf.x[e] = wmma::__float_to_tf32(bf.x[e]);
                wmma::mma_sync(sacc[j], af, bf, sacc[j]);
            }
        }
        #pragma unroll
        for (int j = 0; j < 2; j++)
            wmma::store_matrix_sync(&S[(wm * 16) * SP + kt * 64 + wn * 32 + j * 16],
                                    sacc[j], SP, wmma::mem_row_major);
    }
    __syncthreads();

    // pass 2: scale + alibi + mask, softmax, normalize in place
    {
        int r = tid >> 2, p = tid & 3;
        int ig = qt * 64 + r;
        float* Srow = S + r * SP;
        int base = p * 128;
        float mx = -3e38f;
        for (int jj = 0; jj < 128; jj++) {
            int j = base + jj;
            float s;
            if (mask[b * L_SEQ + j] != 0)
                s = Srow[j] * scale - slope * fabsf((float)(ig - j));
            else
                s = -1e9f;
            Srow[j] = s;
            mx = fmaxf(mx, s);
        }
        red[r * 4 + p] = mx;
        __syncthreads();
        if (p == 0)
            rowmax[r] = fmaxf(fmaxf(red[r * 4], red[r * 4 + 1]),
                              fmaxf(red[r * 4 + 2], red[r * 4 + 3]));
        __syncthreads();
        float rm = rowmax[r];
        float sum = 0.f;
        for (int jj = 0; jj < 128; jj++) {
            float e = __expf(Srow[base + jj] - rm);
            Srow[base + jj] = e;
            sum += e;
        }
        __syncthreads();
        red[r * 4 + p] = sum;
        __syncthreads();
        if (p == 0)
            rowsum[r] = red[r * 4] + red[r * 4 + 1] + red[r * 4 + 2] + red[r * 4 + 3];
        __syncthreads();
        float inv = 1.f / rowsum[r];
        for (int jj = 0; jj < 128; jj++)
            Srow[base + jj] *= inv;
    }

    // pass 3: O = P @ V via wmma (P normalized in smem)
    wmma::fragment<wmma::accumulator, 16, 16, 8, float> oacc[2];
    wmma::fill_fragment(oacc[0], 0.0f);
    wmma::fill_fragment(oacc[1], 0.0f);
    for (int vt = 0; vt < 8; vt++) {
        __syncthreads();
        {
            int r = tid >> 2, c = (tid & 3) * 4;
            const float* vp = v + (size_t)(b * L_SEQ + vt * 64 + r) * HDIM + h * DHEAD;
            #pragma unroll
            for (int p = 0; p < 4; p++)
                *(float4*)&Ks[r * 72 + c + p * 16] = *(const float4*)(vp + c + p * 16);
        }
        __syncthreads();
        #pragma unroll
        for (int kk = 0; kk < 8; kk++) {
            wmma::fragment<wmma::matrix_a, 16, 16, 8, wmma::precision::tf32, wmma::row_major> af;
            wmma::load_matrix_sync(af, &S[(wm * 16) * SP + vt * 64 + kk * 8], SP);
            #pragma unroll
            for (int e = 0; e < af.num_elements; e++)
                af.x[e] = wmma::__float_to_tf32(af.x[e]);
            #pragma unroll
            for (int j = 0; j < 2; j++) {
                wmma::fragment<wmma::matrix_b, 16, 16, 8, wmma::precision::tf32, wmma::row_major> bf;
                wmma::load_matrix_sync(bf, &Ks[(kk * 8) * 72 + wn * 32 + j * 16], 72);
                #pragma unroll
                for (int e = 0; e < bf.num_elements; e++)
                    bf.x[e] = wmma::__float_to_tf32(bf.x[e]);
                wmma::mma_sync(oacc[j], af, bf, oacc[j]);
            }
        }
    }
    #pragma unroll
    for (int j = 0; j < 2; j++)
        wmma::store_matrix_sync(o + (size_t)(b * L_SEQ + qt * 64 + wm * 16) * HDIM
                                  + h * DHEAD + wn * 32 + j * 16,
                                oacc[j], HDIM, wmma::mem_row_major);
}

// ---------------- GEGLU with fused b1 bias -----------------------------------
__global__ void glu_kernel(const float* __restrict__ u,
                           const float* __restrict__ b1,
                           float* __restrict__ ua) {
    int idx = blockIdx.x * blockDim.x + threadIdx.x;
    int m = idx >> 10, i = idx & 1023;
    float val  = u[(size_t)m * 2048 + i] + b1[i];
    float gate = u[(size_t)m * 2048 + 1024 + i] + b1[1024 + i];
    ua[idx] = val * gate * normcdff(gate);
}

// ---------------- final projection to 2 logits -------------------------------
__global__ void out_kernel(const float* __restrict__ hh,
                           const float* __restrict__ Wout,
                           const float* __restrict__ bout,
                           float* __restrict__ out) {
    int row = blockIdx.x;
    int d = threadIdx.x;
    float v = hh[(size_t)row * D_MODEL + d];
    float s0 = v * Wout[d * 2 + 0];
    float s1 = v * Wout[d * 2 + 1];
    #pragma unroll
    for (int o2 = 16; o2 > 0; o2 >>= 1) {
        s0 += __shfl_down_sync(0xffffffffu, s0, o2);
        s1 += __shfl_down_sync(0xffffffffu, s1, o2);
    }
    __shared__ float w0[8], w1[8];
    int w = threadIdx.x >> 5, lane = threadIdx.x & 31;
    if (lane == 0) { w0[w] = s0; w1[w] = s1; }
    __syncthreads();
    if (threadIdx.x == 0) {
        float t0 = 0.f, t1 = 0.f;
        #pragma unroll
        for (int i = 0; i < 8; i++) { t0 += w0[i]; t1 += w1[i]; }
        out[row * 2 + 0] = t0 + bout[0];
        out[row * 2 + 1] = t1 + bout[1];
    }
}

// ---------------- host orchestration -----------------------------------------
extern "C" void kernel_launch(void* const* d_in, const int* in_sizes, int n_in,
                              void* d_out, int out_size) {
    (void)in_sizes; (void)n_in; (void)out_size;
    const int*   seq  = (const int*)d_in[0];
    const int*   mask = (const int*)d_in[1];
    const float* emb  = (const float*)d_in[2];
    const float* png  = (const float*)d_in[3];
    const float* pnb  = (const float*)d_in[4];
    const float* ln1g = (const float*)d_in[5];
    const float* ln1b = (const float*)d_in[6];
    const float* Wq   = (const float*)d_in[7];
    const float* Wk   = (const float*)d_in[8];
    const float* Wv   = (const float*)d_in[9];
    const float* Wo   = (const float*)d_in[10];
    const float* ln2g = (const float*)d_in[11];
    const float* ln2b = (const float*)d_in[12];
    const float* W1   = (const float*)d_in[13];
    const float* b1   = (const float*)d_in[14];
    const float* W2   = (const float*)d_in[15];
    const float* b2   = (const float*)d_in[16];
    const float* fng  = (const float*)d_in[17];
    const float* fnb  = (const float*)d_in[18];
    const float* Wout = (const float*)d_in[19];
    const float* bout = (const float*)d_in[20];

    float *x, *h, *t, *qb, *kb, *vb, *ab, *ub, *uab;
    cudaGetSymbolAddress((void**)&x,   g_x);
    cudaGetSymbolAddress((void**)&h,   g_h);
    cudaGetSymbolAddress((void**)&t,   g_t);
    cudaGetSymbolAddress((void**)&qb,  g_q);
    cudaGetSymbolAddress((void**)&kb,  g_k);
    cudaGetSymbolAddress((void**)&vb,  g_v);
    cudaGetSymbolAddress((void**)&ab,  g_attn);
    cudaGetSymbolAddress((void**)&ub,  g_u);
    cudaGetSymbolAddress((void**)&uab, g_ua);

    const int attn_smem = (2 * 64 * 72 + 64 * SP + 256 + 64 + 64) * (int)sizeof(float);
    cudaFuncSetAttribute(attn_kernel, cudaFuncAttributeMaxDynamicSharedMemorySize, attn_smem);

    embed_ln_kernel<<<M_TOK, 256>>>(seq, emb, png, pnb, x);
    ln_kernel<<<M_TOK, 256>>>(x, ln1g, ln1b, h);

    for (int l = 0; l < DEPTH_N; l++) {
        const float* wq  = Wq  + (size_t)l * D_MODEL * HDIM;
        const float* wk  = Wk  + (size_t)l * D_MODEL * HDIM;
        const float* wv  = Wv  + (size_t)l * D_MODEL * HDIM;
        const float* wo  = Wo  + (size_t)l * HDIM * D_MODEL;
        const float* w1  = W1  + (size_t)l * D_MODEL * 2 * INNER_N;
        const float* bb1 = b1  + (size_t)l * 2 * INNER_N;
        const float* w2  = W2  + (size_t)l * INNER_N * D_MODEL;
        const float* bb2 = b2  + (size_t)l * D_MODEL;

        gemm_tf32<<<dim3(HDIM / 64, 32), 256>>>(h, wq, qb, HDIM, D_MODEL);
        gemm_tf32<<<dim3(HDIM / 64, 32), 256>>>(h, wk, kb, HDIM, D_MODEL);
        gemm_tf32<<<dim3(HDIM / 64, 32), 256>>>(h, wv, vb, HDIM, D_MODEL);

        attn_kernel<<<dim3(L_SEQ / 64, 8 * NHEAD), 256, attn_smem>>>(qb, kb, vb, mask, ab);

        gemm_tf32<<<dim3(D_MODEL / 64, 32), 256>>>(ab, wo, t, D_MODEL, HDIM);
        add_ln_kernel<<<M_TOK, 256>>>(x, t, nullptr, ln2g + l * D_MODEL, ln2b + l * D_MODEL, h);

        gemm_tf32<<<dim3(2 * INNER_N / 64, 32), 256>>>(h, w1, ub, 2 * INNER_N, D_MODEL);
        glu_kernel<<<(M_TOK * INNER_N) / 256, 256>>>(ub, bb1, uab);

        gemm_tf32<<<dim3(D_MODEL / 64, 32), 256>>>(uab, w2, t, D_MODEL, INNER_N);
        if (l < DEPTH_N - 1)
            add_ln_kernel<<<M_TOK, 256>>>(x, t, bb2, ln1g + (l + 1) * D_MODEL,
                                          ln1b + (l + 1) * D_MODEL, h);
        else
            add_ln_kernel<<<M_TOK, 256>>>(x, t, bb2, fng, fnb, h);
    }

    out_kernel<<<M_TOK, 256>>>(h, Wout, bout, (float*)d_out);
}